// round 1
// baseline (speedup 1.0000x reference)
#include <cuda_runtime.h>

// Problem constants
#define LSEQ 512
#define NH 12
#define FD 16
#define HD 64
#define DM 768
#define DREAL 273
#define DP 288          // padded feature dim (zeros in 273..287)
#define CH 8            // number of chunks
#define CT 64           // chunk length
#define PROJ_N 1152     // q(192) | k(192) | v(768)
#define EPSV 1e-12f

// Scratch (device globals; no allocation allowed)
__device__ float g_P[LSEQ * PROJ_N];            // projection output
__device__ float g_phiQ[NH * LSEQ * DP];
__device__ float g_phiK[NH * LSEQ * DP];
__device__ float g_S[NH * CH * DP * HD];        // chunk KV sums -> exclusive prefix states
__device__ float g_Z[NH * CH * DP];             // chunk k sums  -> exclusive prefix
__device__ float g_Y[LSEQ * DM];                // attention output (pre-Wo)

// ---------------------------------------------------------------------------
// Tiled fp32 GEMM: C[m, ncol0+n] = sum_k A[m,k] * B[n,k]
// BM=BN=64, BK=16, 256 threads, 4x4 micro-tile. All dims divisible (K=768).
// ---------------------------------------------------------------------------
__device__ __forceinline__ void gemm_abt_body(
    const float* __restrict__ A, const float* __restrict__ B,
    float* __restrict__ C, int K, int ldc, int ncol0)
{
    __shared__ __align__(16) float As[16][68];
    __shared__ __align__(16) float Bs[16][68];
    const int tid = threadIdx.x;
    const int tx = tid & 15, ty = tid >> 4;
    const int row0 = blockIdx.x * 64, col0 = blockIdx.y * 64;
    const int lr = tid >> 2;            // 0..63
    const int lk = (tid & 3) * 4;       // 0,4,8,12

    float acc[4][4];
#pragma unroll
    for (int i = 0; i < 4; i++)
#pragma unroll
        for (int j = 0; j < 4; j++) acc[i][j] = 0.f;

    for (int k0 = 0; k0 < K; k0 += 16) {
        float4 av = *(const float4*)&A[(size_t)(row0 + lr) * K + k0 + lk];
        float4 bv = *(const float4*)&B[(size_t)(col0 + lr) * K + k0 + lk];
        As[lk + 0][lr] = av.x; As[lk + 1][lr] = av.y;
        As[lk + 2][lr] = av.z; As[lk + 3][lr] = av.w;
        Bs[lk + 0][lr] = bv.x; Bs[lk + 1][lr] = bv.y;
        Bs[lk + 2][lr] = bv.z; Bs[lk + 3][lr] = bv.w;
        __syncthreads();
#pragma unroll
        for (int kk = 0; kk < 16; kk++) {
            float4 a = *(const float4*)&As[kk][ty * 4];
            float4 b = *(const float4*)&Bs[kk][tx * 4];
            acc[0][0] += a.x * b.x; acc[0][1] += a.x * b.y; acc[0][2] += a.x * b.z; acc[0][3] += a.x * b.w;
            acc[1][0] += a.y * b.x; acc[1][1] += a.y * b.y; acc[1][2] += a.y * b.z; acc[1][3] += a.y * b.w;
            acc[2][0] += a.z * b.x; acc[2][1] += a.z * b.y; acc[2][2] += a.z * b.z; acc[2][3] += a.z * b.w;
            acc[3][0] += a.w * b.x; acc[3][1] += a.w * b.y; acc[3][2] += a.w * b.z; acc[3][3] += a.w * b.w;
        }
        __syncthreads();
    }
#pragma unroll
    for (int i = 0; i < 4; i++)
#pragma unroll
        for (int j = 0; j < 4; j++)
            C[(size_t)(row0 + ty * 4 + i) * ldc + ncol0 + col0 + tx * 4 + j] = acc[i][j];
}

__global__ void gemm_proj_kernel(const float* __restrict__ A, const float* __restrict__ B,
                                 int K, int ncol0)
{
    gemm_abt_body(A, B, g_P, K, PROJ_N, ncol0);
}

__global__ void gemm_out_kernel(const float* __restrict__ Wo, float* __restrict__ out)
{
    gemm_abt_body(g_Y, Wo, out, DM, DM, 0);
}

// ---------------------------------------------------------------------------
// Taylor feature map: phi = [1, x/2, x_i*x_j/(4*sqrt(2))], padded with zeros.
// grid (512, 12), 288 threads
// ---------------------------------------------------------------------------
__global__ void phi_kernel()
{
    const int l = blockIdx.x, h = blockIdx.y, d = threadIdx.x;
    __shared__ float xq[16], xk[16];
    if (d < 16) {
        xq[d] = g_P[l * PROJ_N + h * FD + d];
        xk[d] = g_P[l * PROJ_N + 192 + h * FD + d];
    }
    __syncthreads();
    float vq = 0.f, vk = 0.f;
    if (d == 0) { vq = 1.f; vk = 1.f; }
    else if (d <= 16) { vq = xq[d - 1] * 0.5f; vk = xk[d - 1] * 0.5f; }
    else if (d < DREAL) {
        const int e = d - 17;
        const int i = e >> 4, j = e & 15;
        const float s = 0.17677669529663687f;   // 1/(4*sqrt(2))
        vq = xq[i] * xq[j] * s;
        vk = xk[i] * xk[j] * s;
    }
    const size_t base = (size_t)(h * LSEQ + l) * DP + d;
    g_phiQ[base] = vq;
    g_phiK[base] = vk;
}

// ---------------------------------------------------------------------------
// Per-chunk local sums: S_local[d][j] = sum_t phiK[t][d]*V[t][j]; z[d]=sum_t phiK
// grid (CH, NH), 288 threads (one per feature d)
// ---------------------------------------------------------------------------
__global__ void chunk_kv_kernel()
{
    const int c = blockIdx.x, h = blockIdx.y;
    __shared__ __align__(16) float sV[CT][68];
    const int tid = threadIdx.x;
    for (int idx = tid; idx < CT * HD; idx += 288) {
        const int t = idx >> 6, j = idx & 63;
        sV[t][j] = g_P[(size_t)(c * CT + t) * PROJ_N + 384 + h * HD + j];
    }
    __syncthreads();

    const int d = tid;      // 0..287
    float4 acc[16];
#pragma unroll
    for (int i = 0; i < 16; i++) acc[i] = make_float4(0.f, 0.f, 0.f, 0.f);
    float zs = 0.f;

    const float* pk = &g_phiK[(size_t)(h * LSEQ + c * CT) * DP + d];
#pragma unroll 4
    for (int t = 0; t < CT; t++) {
        const float kd = pk[(size_t)t * DP];
        zs += kd;
#pragma unroll
        for (int j4 = 0; j4 < 16; j4++) {
            float4 v = *(const float4*)&sV[t][j4 * 4];
            acc[j4].x += kd * v.x; acc[j4].y += kd * v.y;
            acc[j4].z += kd * v.z; acc[j4].w += kd * v.w;
        }
    }
    float* outp = &g_S[((size_t)(h * CH + c) * DP + d) * HD];
#pragma unroll
    for (int j4 = 0; j4 < 16; j4++) *(float4*)&outp[j4 * 4] = acc[j4];
    g_Z[(size_t)(h * CH + c) * DP + d] = zs;
}

// ---------------------------------------------------------------------------
// Exclusive prefix over chunks (in place). grid NH, 288 threads
// ---------------------------------------------------------------------------
__global__ void prefix_kernel()
{
    const int h = blockIdx.x;
    const int d = threadIdx.x;
    float4 carry[16];
#pragma unroll
    for (int i = 0; i < 16; i++) carry[i] = make_float4(0.f, 0.f, 0.f, 0.f);
    float zc = 0.f;
    for (int c = 0; c < CH; c++) {
        float* p = &g_S[((size_t)(h * CH + c) * DP + d) * HD];
#pragma unroll
        for (int j4 = 0; j4 < 16; j4++) {
            float4 v = *(const float4*)&p[j4 * 4];
            *(float4*)&p[j4 * 4] = carry[j4];
            carry[j4].x += v.x; carry[j4].y += v.y;
            carry[j4].z += v.z; carry[j4].w += v.w;
        }
        const size_t zi = (size_t)(h * CH + c) * DP + d;
        const float z = g_Z[zi];
        g_Z[zi] = zc;
        zc += z;
    }
}

// ---------------------------------------------------------------------------
// Per-chunk attention output:
//   A = tril(phiQ phiK^T)  [64x64]
//   Y = phiQ @ S_prev + A @ V
//   den = phiQ . z_prev + rowsum(A) + eps
//   y = Y / den
// grid (CH, NH), 256 threads
// ---------------------------------------------------------------------------
__global__ void attn_out_kernel()
{
    const int c = blockIdx.x, h = blockIdx.y;
    __shared__ __align__(16) float sA[CT][68];
    __shared__ __align__(16) float sV[CT][68];
    __shared__ float sQ[CT][17];
    __shared__ float sK[CT][17];
    __shared__ __align__(16) float sS[16][68];
    __shared__ float sZ[16];
    __shared__ float sDen[CT];

    const int tid = threadIdx.x;
    const int tx = tid & 15, ty = tid >> 4;
    const int ty4 = ty * 4, tx4 = tx * 4;

    // load V chunk
    for (int idx = tid; idx < CT * HD; idx += 256) {
        const int t = idx >> 6, j = idx & 63;
        sV[t][j] = g_P[(size_t)(c * CT + t) * PROJ_N + 384 + h * HD + j];
    }

    const float* phq = &g_phiQ[(size_t)(h * LSEQ + c * CT) * DP];
    const float* phk = &g_phiK[(size_t)(h * LSEQ + c * CT) * DP];
    const int lr = tid >> 2;
    const int lc = (tid & 3) * 4;

    // ---- Phase 1: A = phiQ phiK^T ----
    float acc[4][4];
#pragma unroll
    for (int i = 0; i < 4; i++)
#pragma unroll
        for (int j = 0; j < 4; j++) acc[i][j] = 0.f;

    for (int d0 = 0; d0 < DP; d0 += 16) {
        float4 qv = *(const float4*)&phq[(size_t)lr * DP + d0 + lc];
        float4 kv = *(const float4*)&phk[(size_t)lr * DP + d0 + lc];
        sQ[lr][lc + 0] = qv.x; sQ[lr][lc + 1] = qv.y; sQ[lr][lc + 2] = qv.z; sQ[lr][lc + 3] = qv.w;
        sK[lr][lc + 0] = kv.x; sK[lr][lc + 1] = kv.y; sK[lr][lc + 2] = kv.z; sK[lr][lc + 3] = kv.w;
        __syncthreads();
#pragma unroll
        for (int dd = 0; dd < 16; dd++) {
            float a0 = sQ[ty4 + 0][dd], a1 = sQ[ty4 + 1][dd], a2 = sQ[ty4 + 2][dd], a3 = sQ[ty4 + 3][dd];
            float b0 = sK[tx4 + 0][dd], b1 = sK[tx4 + 1][dd], b2 = sK[tx4 + 2][dd], b3 = sK[tx4 + 3][dd];
            acc[0][0] += a0 * b0; acc[0][1] += a0 * b1; acc[0][2] += a0 * b2; acc[0][3] += a0 * b3;
            acc[1][0] += a1 * b0; acc[1][1] += a1 * b1; acc[1][2] += a1 * b2; acc[1][3] += a1 * b3;
            acc[2][0] += a2 * b0; acc[2][1] += a2 * b1; acc[2][2] += a2 * b2; acc[2][3] += a2 * b3;
            acc[3][0] += a3 * b0; acc[3][1] += a3 * b1; acc[3][2] += a3 * b2; acc[3][3] += a3 * b3;
        }
        __syncthreads();
    }
    // store causally-masked A
#pragma unroll
    for (int i = 0; i < 4; i++)
#pragma unroll
        for (int j = 0; j < 4; j++) {
            const int t = ty4 + i, s = tx4 + j;
            sA[t][s] = (s <= t) ? acc[i][j] : 0.f;
        }
    __syncthreads();

    // ---- Phase 2: Y = phiQ @ S_prev (+ den partial phiQ.z_prev) ----
    float y00 = 0.f, y01 = 0.f, y02 = 0.f, y03 = 0.f;
    float y10 = 0.f, y11 = 0.f, y12 = 0.f, y13 = 0.f;
    float y20 = 0.f, y21 = 0.f, y22 = 0.f, y23 = 0.f;
    float y30 = 0.f, y31 = 0.f, y32 = 0.f, y33 = 0.f;
    float den0 = 0.f, den1 = 0.f, den2 = 0.f, den3 = 0.f;

    const float* Sp = &g_S[(size_t)(h * CH + c) * DP * HD];
    const float* Zp = &g_Z[(size_t)(h * CH + c) * DP];

    for (int d0 = 0; d0 < DP; d0 += 16) {
        float4 qv = *(const float4*)&phq[(size_t)lr * DP + d0 + lc];
        sQ[lr][lc + 0] = qv.x; sQ[lr][lc + 1] = qv.y; sQ[lr][lc + 2] = qv.z; sQ[lr][lc + 3] = qv.w;
        float4 sv = *(const float4*)&Sp[(size_t)(d0 + (tid >> 4)) * HD + (tid & 15) * 4];
        *(float4*)&sS[tid >> 4][(tid & 15) * 4] = sv;
        if (tid < 16) sZ[tid] = Zp[d0 + tid];
        __syncthreads();
#pragma unroll
        for (int dd = 0; dd < 16; dd++) {
            float a0 = sQ[ty4 + 0][dd], a1 = sQ[ty4 + 1][dd], a2 = sQ[ty4 + 2][dd], a3 = sQ[ty4 + 3][dd];
            float4 b = *(const float4*)&sS[dd][tx4];
            y00 += a0 * b.x; y01 += a0 * b.y; y02 += a0 * b.z; y03 += a0 * b.w;
            y10 += a1 * b.x; y11 += a1 * b.y; y12 += a1 * b.z; y13 += a1 * b.w;
            y20 += a2 * b.x; y21 += a2 * b.y; y22 += a2 * b.z; y23 += a2 * b.w;
            y30 += a3 * b.x; y31 += a3 * b.y; y32 += a3 * b.z; y33 += a3 * b.w;
            if (tx == 0) {
                const float z = sZ[dd];
                den0 += a0 * z; den1 += a1 * z; den2 += a2 * z; den3 += a3 * z;
            }
        }
        __syncthreads();
    }

    // ---- Phase 3: Y += A @ V (A already masked) ----
#pragma unroll 4
    for (int s = 0; s < CT; s++) {
        float a0 = sA[ty4 + 0][s], a1 = sA[ty4 + 1][s], a2 = sA[ty4 + 2][s], a3 = sA[ty4 + 3][s];
        float4 b = *(const float4*)&sV[s][tx4];
        y00 += a0 * b.x; y01 += a0 * b.y; y02 += a0 * b.z; y03 += a0 * b.w;
        y10 += a1 * b.x; y11 += a1 * b.y; y12 += a1 * b.z; y13 += a1 * b.w;
        y20 += a2 * b.x; y21 += a2 * b.y; y22 += a2 * b.z; y23 += a2 * b.w;
        y30 += a3 * b.x; y31 += a3 * b.y; y32 += a3 * b.z; y33 += a3 * b.w;
    }

    // ---- den: add rowsums of masked A ----
    if (tx == 0) {
        float r0 = den0 + EPSV, r1 = den1 + EPSV, r2 = den2 + EPSV, r3 = den3 + EPSV;
#pragma unroll 8
        for (int s = 0; s < CT; s++) {
            r0 += sA[ty4 + 0][s];
            r1 += sA[ty4 + 1][s];
            r2 += sA[ty4 + 2][s];
            r3 += sA[ty4 + 3][s];
        }
        sDen[ty4 + 0] = r0; sDen[ty4 + 1] = r1; sDen[ty4 + 2] = r2; sDen[ty4 + 3] = r3;
    }
    __syncthreads();

    const float i0 = 1.f / sDen[ty4 + 0];
    const float i1 = 1.f / sDen[ty4 + 1];
    const float i2 = 1.f / sDen[ty4 + 2];
    const float i3 = 1.f / sDen[ty4 + 3];
    float* yo = &g_Y[(size_t)(c * CT) * DM + h * HD + tx4];
    {
        float4 o;
        o.x = y00 * i0; o.y = y01 * i0; o.z = y02 * i0; o.w = y03 * i0;
        *(float4*)&yo[(size_t)(ty4 + 0) * DM] = o;
        o.x = y10 * i1; o.y = y11 * i1; o.z = y12 * i1; o.w = y13 * i1;
        *(float4*)&yo[(size_t)(ty4 + 1) * DM] = o;
        o.x = y20 * i2; o.y = y21 * i2; o.z = y22 * i2; o.w = y23 * i2;
        *(float4*)&yo[(size_t)(ty4 + 2) * DM] = o;
        o.x = y30 * i3; o.y = y31 * i3; o.z = y32 * i3; o.w = y33 * i3;
        *(float4*)&yo[(size_t)(ty4 + 3) * DM] = o;
    }
}

// ---------------------------------------------------------------------------
extern "C" void kernel_launch(void* const* d_in, const int* in_sizes, int n_in,
                              void* d_out, int out_size)
{
    const float* hs = (const float*)d_in[0];
    const float* Wq = (const float*)d_in[1];
    const float* Wk = (const float*)d_in[2];
    const float* Wv = (const float*)d_in[3];
    const float* Wo = (const float*)d_in[4];
    float* out = (float*)d_out;

    // projections: P[:, 0:192]=q, [192:384]=k, [384:1152]=v
    gemm_proj_kernel<<<dim3(8, 3), 256>>>(hs, Wq, DM, 0);
    gemm_proj_kernel<<<dim3(8, 3), 256>>>(hs, Wk, DM, 192);
    gemm_proj_kernel<<<dim3(8, 12), 256>>>(hs, Wv, DM, 384);

    // feature maps
    phi_kernel<<<dim3(LSEQ, NH), DP>>>();

    // chunked linear attention
    chunk_kv_kernel<<<dim3(CH, NH), DP>>>();
    prefix_kernel<<<NH, DP>>>();
    attn_out_kernel<<<dim3(CH, NH), 256>>>();

    // output projection
    gemm_out_kernel<<<dim3(8, 12), 256>>>(Wo, out);
}

// round 3
// speedup vs baseline: 1.0312x; 1.0312x over previous
#include <cuda_runtime.h>

typedef unsigned long long ull;

// Problem constants
#define LSEQ 512
#define NH 12
#define FD 16
#define HD 64
#define DM 768
#define DREAL 273
#define DP 288          // padded feature dim (zeros in 273..287)
#define CH 8            // number of chunks
#define CT 64           // chunk length
#define PROJ_N 1152     // q(192) | k(192) | v(768)
#define EPSV 1e-12f

// Scratch (device globals; no allocation allowed)
__device__ float g_P[LSEQ * PROJ_N];            // projection output
__device__ float g_phiQ[NH * LSEQ * DP];
__device__ float g_phiK[NH * LSEQ * DP];
__device__ float g_S[NH * CH * DP * HD];        // chunk KV sums -> exclusive prefix states
__device__ float g_Z[NH * CH * DP];             // chunk k sums  -> exclusive prefix
__device__ float g_Y[LSEQ * DM];                // attention output (pre-Wo)

// ---------------------------------------------------------------------------
// Packed f32x2 helpers (Blackwell FFMA2 path — only reachable via PTX)
// ---------------------------------------------------------------------------
__device__ __forceinline__ ull dup2(float a) {
    ull r; asm("mov.b64 %0, {%1, %1};" : "=l"(r) : "f"(a)); return r;
}
__device__ __forceinline__ void fma2(ull& d, ull a, ull b) {
    asm("fma.rn.f32x2 %0, %1, %2, %0;" : "+l"(d) : "l"(a), "l"(b));
}
__device__ __forceinline__ float2 unpk(ull v) {
    float2 r; asm("mov.b64 {%0, %1}, %2;" : "=f"(r.x), "=f"(r.y) : "l"(v)); return r;
}

// ---------------------------------------------------------------------------
// Tiled fp32 GEMM: C[row0+m, coff+n] = sum_k A[row0+m,k] * B[n,k]
// BM=BN=64, BK=16, 256 threads, 4x4 micro-tile, packed FFMA2, double-buffered.
// ---------------------------------------------------------------------------
__device__ __forceinline__ void gemm_body(
    const float* __restrict__ A, const float* __restrict__ B,
    float* __restrict__ C, int K, int ldc, int coff, int row0)
{
    __shared__ __align__(16) float As[2][16][68];
    __shared__ __align__(16) float Bs[2][16][68];
    const int tid = threadIdx.x;
    const int tx = tid & 15, ty = tid >> 4;
    const int lr = tid >> 2;            // 0..63
    const int lk = (tid & 3) * 4;       // 0,4,8,12

    ull acc[4][2];
#pragma unroll
    for (int i = 0; i < 4; i++) { acc[i][0] = 0ull; acc[i][1] = 0ull; }

    const float* ap = &A[(size_t)(row0 + lr) * K + lk];
    const float* bp = &B[(size_t)lr * K + lk];

    // preload tile 0
    {
        float4 av = *(const float4*)ap;
        float4 bv = *(const float4*)bp;
        As[0][lk + 0][lr] = av.x; As[0][lk + 1][lr] = av.y;
        As[0][lk + 2][lr] = av.z; As[0][lk + 3][lr] = av.w;
        Bs[0][lk + 0][lr] = bv.x; Bs[0][lk + 1][lr] = bv.y;
        Bs[0][lk + 2][lr] = bv.z; Bs[0][lk + 3][lr] = bv.w;
    }
    __syncthreads();

    int buf = 0;
    for (int k0 = 0; k0 < K; k0 += 16) {
        float4 av2, bv2;
        const bool more = (k0 + 16 < K);
        if (more) {
            av2 = *(const float4*)(ap + k0 + 16);
            bv2 = *(const float4*)(bp + k0 + 16);
        }
#pragma unroll
        for (int kk = 0; kk < 16; kk++) {
            float4 a = *(const float4*)&As[buf][kk][ty * 4];
            ulonglong2 b = *(const ulonglong2*)&Bs[buf][kk][tx * 4];
            ull a0 = dup2(a.x), a1 = dup2(a.y), a2 = dup2(a.z), a3 = dup2(a.w);
            fma2(acc[0][0], a0, b.x); fma2(acc[0][1], a0, b.y);
            fma2(acc[1][0], a1, b.x); fma2(acc[1][1], a1, b.y);
            fma2(acc[2][0], a2, b.x); fma2(acc[2][1], a2, b.y);
            fma2(acc[3][0], a3, b.x); fma2(acc[3][1], a3, b.y);
        }
        if (more) {
            const int nb = buf ^ 1;
            As[nb][lk + 0][lr] = av2.x; As[nb][lk + 1][lr] = av2.y;
            As[nb][lk + 2][lr] = av2.z; As[nb][lk + 3][lr] = av2.w;
            Bs[nb][lk + 0][lr] = bv2.x; Bs[nb][lk + 1][lr] = bv2.y;
            Bs[nb][lk + 2][lr] = bv2.z; Bs[nb][lk + 3][lr] = bv2.w;
        }
        __syncthreads();
        buf ^= 1;
    }

#pragma unroll
    for (int i = 0; i < 4; i++) {
        float2 p0 = unpk(acc[i][0]);
        float2 p1 = unpk(acc[i][1]);
        float4 o; o.x = p0.x; o.y = p0.y; o.z = p1.x; o.w = p1.y;
        *(float4*)&C[(size_t)(row0 + ty * 4 + i) * ldc + coff + tx * 4] = o;
    }
}

// Fused q|k|v projection: grid (8, 18)
__global__ __launch_bounds__(256) void gemm_proj_fused(
    const float* __restrict__ hs, const float* __restrict__ Wq,
    const float* __restrict__ Wk, const float* __restrict__ Wv)
{
    const int cb = blockIdx.y;
    const float* B; int coff;
    if (cb < 3)      { B = Wq + (size_t)cb * 64 * DM;        coff = cb * 64; }
    else if (cb < 6) { B = Wk + (size_t)(cb - 3) * 64 * DM;  coff = 192 + (cb - 3) * 64; }
    else             { B = Wv + (size_t)(cb - 6) * 64 * DM;  coff = 384 + (cb - 6) * 64; }
    gemm_body(hs, B, g_P, DM, PROJ_N, coff, blockIdx.x * 64);
}

// Output projection: grid (8, 12)
__global__ __launch_bounds__(256) void gemm_out_kernel(
    const float* __restrict__ Wo, float* __restrict__ out)
{
    gemm_body(g_Y, Wo + (size_t)blockIdx.y * 64 * DM, out, DM, DM,
              blockIdx.y * 64, blockIdx.x * 64);
}

// ---------------------------------------------------------------------------
// Taylor feature map: phi = [1, x/2, x_i*x_j/(4*sqrt(2))], padded with zeros.
// grid (512), 288 threads — each block handles one sequence position, all heads
// ---------------------------------------------------------------------------
__global__ void phi_kernel()
{
    const int l = blockIdx.x, d = threadIdx.x;
    __shared__ float sx[384];
    for (int i = d; i < 384; i += 288) sx[i] = g_P[(size_t)l * PROJ_N + i];
    __syncthreads();

    int ii = 0, jj = 0, mode;
    if (d == 0) mode = 0;
    else if (d <= 16) { mode = 1; ii = d - 1; }
    else if (d < DREAL) { mode = 2; const int e = d - 17; ii = e >> 4; jj = e & 15; }
    else mode = 3;

    const float s = 0.17677669529663687f;   // 1/(4*sqrt(2))
    const size_t base = (size_t)l * DP + d;
#pragma unroll
    for (int h = 0; h < NH; h++) {
        const float* xq = &sx[h * FD];
        const float* xk = &sx[192 + h * FD];
        float vq, vk;
        if (mode == 0)      { vq = 1.f; vk = 1.f; }
        else if (mode == 1) { vq = xq[ii] * 0.5f; vk = xk[ii] * 0.5f; }
        else if (mode == 2) { vq = xq[ii] * xq[jj] * s; vk = xk[ii] * xk[jj] * s; }
        else                { vq = 0.f; vk = 0.f; }
        g_phiQ[(size_t)h * LSEQ * DP + base] = vq;
        g_phiK[(size_t)h * LSEQ * DP + base] = vk;
    }
}

// ---------------------------------------------------------------------------
// Per-chunk local sums: S_local[d][j] = sum_t phiK[t][d]*V[t][j]; z[d]=sum_t phiK
// grid (CH, NH), 288 threads (one per feature d), packed FFMA2
// ---------------------------------------------------------------------------
__global__ void chunk_kv_kernel()
{
    const int c = blockIdx.x, h = blockIdx.y;
    __shared__ __align__(16) float sV[CT][68];
    const int tid = threadIdx.x;
    for (int idx = tid; idx < CT * HD; idx += 288) {
        const int t = idx >> 6, j = idx & 63;
        sV[t][j] = g_P[(size_t)(c * CT + t) * PROJ_N + 384 + h * HD + j];
    }
    __syncthreads();

    const int d = tid;      // 0..287
    ull acc[32];
#pragma unroll
    for (int i = 0; i < 32; i++) acc[i] = 0ull;
    float zs = 0.f;

    const float* pk = &g_phiK[(size_t)(h * LSEQ + c * CT) * DP + d];
#pragma unroll 2
    for (int t = 0; t < CT; t++) {
        const float kd = pk[(size_t)t * DP];
        zs += kd;
        const ull kdp = dup2(kd);
#pragma unroll
        for (int j = 0; j < 16; j++) {
            ulonglong2 v = *(const ulonglong2*)&sV[t][j * 4];
            fma2(acc[2 * j + 0], kdp, v.x);
            fma2(acc[2 * j + 1], kdp, v.y);
        }
    }
    float* outp = &g_S[((size_t)(h * CH + c) * DP + d) * HD];
#pragma unroll
    for (int j = 0; j < 16; j++) {
        float2 p0 = unpk(acc[2 * j + 0]);
        float2 p1 = unpk(acc[2 * j + 1]);
        float4 o; o.x = p0.x; o.y = p0.y; o.z = p1.x; o.w = p1.y;
        *(float4*)&outp[j * 4] = o;
    }
    g_Z[(size_t)(h * CH + c) * DP + d] = zs;
}

// ---------------------------------------------------------------------------
// Exclusive prefix over chunks (in place). grid NH, 288 threads
// ---------------------------------------------------------------------------
__global__ void prefix_kernel()
{
    const int h = blockIdx.x;
    const int d = threadIdx.x;
    float4 carry[16];
#pragma unroll
    for (int i = 0; i < 16; i++) carry[i] = make_float4(0.f, 0.f, 0.f, 0.f);
    float zc = 0.f;
    for (int c = 0; c < CH; c++) {
        float* p = &g_S[((size_t)(h * CH + c) * DP + d) * HD];
#pragma unroll
        for (int j4 = 0; j4 < 16; j4++) {
            float4 v = *(const float4*)&p[j4 * 4];
            *(float4*)&p[j4 * 4] = carry[j4];
            carry[j4].x += v.x; carry[j4].y += v.y;
            carry[j4].z += v.z; carry[j4].w += v.w;
        }
        const size_t zi = (size_t)(h * CH + c) * DP + d;
        const float z = g_Z[zi];
        g_Z[zi] = zc;
        zc += z;
    }
}

// ---------------------------------------------------------------------------
// Per-chunk attention output (merged phases, packed FFMA2, reg prefetch):
//   A = tril(phiQ phiK^T);  Y = phiQ @ S_prev + A @ V
//   den = phiQ . z_prev + rowsum(A) + eps;  y = Y / den
// grid (CH, NH), 256 threads
// ---------------------------------------------------------------------------
__global__ __launch_bounds__(256) void attn_out_kernel()
{
    const int c = blockIdx.x, h = blockIdx.y;
    __shared__ __align__(16) float sA[CT][68];
    __shared__ __align__(16) float sV[CT][68];
    __shared__ __align__(16) float sQt[16][68];   // [feature][row] transposed
    __shared__ __align__(16) float sKt[16][68];
    __shared__ __align__(16) float sS[16][68];
    __shared__ float sZ[16];
    __shared__ float sDen[CT];

    const int tid = threadIdx.x;
    const int tx = tid & 15, ty = tid >> 4;
    const int ty4 = ty * 4, tx4 = tx * 4;
    const int lr = tid >> 2;
    const int lc = (tid & 3) * 4;

    // load V chunk
    for (int idx = tid; idx < CT * HD; idx += 256) {
        const int t = idx >> 6, j = idx & 63;
        sV[t][j] = g_P[(size_t)(c * CT + t) * PROJ_N + 384 + h * HD + j];
    }

    const float* phq = &g_phiQ[(size_t)(h * LSEQ + c * CT) * DP];
    const float* phk = &g_phiK[(size_t)(h * LSEQ + c * CT) * DP];
    const float* Sp = &g_S[(size_t)(h * CH + c) * DP * HD];
    const float* Zp = &g_Z[(size_t)(h * CH + c) * DP];

    ull accA[4][2], accY[4][2];
#pragma unroll
    for (int i = 0; i < 4; i++) {
        accA[i][0] = 0ull; accA[i][1] = 0ull;
        accY[i][0] = 0ull; accY[i][1] = 0ull;
    }
    float den0 = 0.f, den1 = 0.f, den2 = 0.f, den3 = 0.f;

    // prefetch first tile
    float4 qv = *(const float4*)&phq[(size_t)lr * DP + lc];
    float4 kv = *(const float4*)&phk[(size_t)lr * DP + lc];
    float4 sv = *(const float4*)&Sp[(size_t)ty * HD + tx4];
    float  zv = (tid < 16) ? Zp[tid] : 0.f;

    for (int d0 = 0; d0 < DP; d0 += 16) {
        // commit current tile to smem
        sQt[lc + 0][lr] = qv.x; sQt[lc + 1][lr] = qv.y;
        sQt[lc + 2][lr] = qv.z; sQt[lc + 3][lr] = qv.w;
        sKt[lc + 0][lr] = kv.x; sKt[lc + 1][lr] = kv.y;
        sKt[lc + 2][lr] = kv.z; sKt[lc + 3][lr] = kv.w;
        *(float4*)&sS[ty][tx4] = sv;
        if (tid < 16) sZ[tid] = zv;
        __syncthreads();

        // prefetch next tile (overlap with compute)
        const int dn = d0 + 16;
        if (dn < DP) {
            qv = *(const float4*)&phq[(size_t)lr * DP + dn + lc];
            kv = *(const float4*)&phk[(size_t)lr * DP + dn + lc];
            sv = *(const float4*)&Sp[(size_t)(dn + ty) * HD + tx4];
            if (tid < 16) zv = Zp[dn + tid];
        }

#pragma unroll
        for (int dd = 0; dd < 16; dd++) {
            float4 a = *(const float4*)&sQt[dd][ty4];
            ulonglong2 kp = *(const ulonglong2*)&sKt[dd][tx4];
            ulonglong2 sp = *(const ulonglong2*)&sS[dd][tx4];
            ull a0 = dup2(a.x), a1 = dup2(a.y), a2 = dup2(a.z), a3 = dup2(a.w);
            fma2(accA[0][0], a0, kp.x); fma2(accA[0][1], a0, kp.y);
            fma2(accA[1][0], a1, kp.x); fma2(accA[1][1], a1, kp.y);
            fma2(accA[2][0], a2, kp.x); fma2(accA[2][1], a2, kp.y);
            fma2(accA[3][0], a3, kp.x); fma2(accA[3][1], a3, kp.y);
            fma2(accY[0][0], a0, sp.x); fma2(accY[0][1], a0, sp.y);
            fma2(accY[1][0], a1, sp.x); fma2(accY[1][1], a1, sp.y);
            fma2(accY[2][0], a2, sp.x); fma2(accY[2][1], a2, sp.y);
            fma2(accY[3][0], a3, sp.x); fma2(accY[3][1], a3, sp.y);
            if (tx == 0) {
                const float z = sZ[dd];
                den0 += a.x * z; den1 += a.y * z; den2 += a.z * z; den3 += a.w * z;
            }
        }
        __syncthreads();
    }

    // mask + store A
#pragma unroll
    for (int i = 0; i < 4; i++) {
        float2 p0 = unpk(accA[i][0]);
        float2 p1 = unpk(accA[i][1]);
        const int t = ty4 + i;
        sA[t][tx4 + 0] = (tx4 + 0 <= t) ? p0.x : 0.f;
        sA[t][tx4 + 1] = (tx4 + 1 <= t) ? p0.y : 0.f;
        sA[t][tx4 + 2] = (tx4 + 2 <= t) ? p1.x : 0.f;
        sA[t][tx4 + 3] = (tx4 + 3 <= t) ? p1.y : 0.f;
    }
    __syncthreads();

    // Y += A @ V (A masked)
#pragma unroll 4
    for (int s = 0; s < CT; s++) {
        float a0s = sA[ty4 + 0][s], a1s = sA[ty4 + 1][s];
        float a2s = sA[ty4 + 2][s], a3s = sA[ty4 + 3][s];
        ulonglong2 v = *(const ulonglong2*)&sV[s][tx4];
        ull a0 = dup2(a0s), a1 = dup2(a1s), a2 = dup2(a2s), a3 = dup2(a3s);
        fma2(accY[0][0], a0, v.x); fma2(accY[0][1], a0, v.y);
        fma2(accY[1][0], a1, v.x); fma2(accY[1][1], a1, v.y);
        fma2(accY[2][0], a2, v.x); fma2(accY[2][1], a2, v.y);
        fma2(accY[3][0], a3, v.x); fma2(accY[3][1], a3, v.y);
    }

    // den: add rowsums of masked A
    if (tx == 0) {
        float r0 = den0 + EPSV, r1 = den1 + EPSV, r2 = den2 + EPSV, r3 = den3 + EPSV;
#pragma unroll 8
        for (int s = 0; s < CT; s++) {
            r0 += sA[ty4 + 0][s];
            r1 += sA[ty4 + 1][s];
            r2 += sA[ty4 + 2][s];
            r3 += sA[ty4 + 3][s];
        }
        sDen[ty4 + 0] = r0; sDen[ty4 + 1] = r1; sDen[ty4 + 2] = r2; sDen[ty4 + 3] = r3;
    }
    __syncthreads();

    float* yo = &g_Y[(size_t)(c * CT) * DM + h * HD + tx4];
#pragma unroll
    for (int i = 0; i < 4; i++) {
        const float inv = 1.f / sDen[ty4 + i];
        float2 p0 = unpk(accY[i][0]);
        float2 p1 = unpk(accY[i][1]);
        float4 o;
        o.x = p0.x * inv; o.y = p0.y * inv; o.z = p1.x * inv; o.w = p1.y * inv;
        *(float4*)&yo[(size_t)(ty4 + i) * DM] = o;
    }
}

// ---------------------------------------------------------------------------
extern "C" void kernel_launch(void* const* d_in, const int* in_sizes, int n_in,
                              void* d_out, int out_size)
{
    const float* hs = (const float*)d_in[0];
    const float* Wq = (const float*)d_in[1];
    const float* Wk = (const float*)d_in[2];
    const float* Wv = (const float*)d_in[3];
    const float* Wo = (const float*)d_in[4];
    float* out = (float*)d_out;

    gemm_proj_fused<<<dim3(8, 18), 256>>>(hs, Wq, Wk, Wv);
    phi_kernel<<<LSEQ, DP>>>();
    chunk_kv_kernel<<<dim3(CH, NH), DP>>>();
    prefix_kernel<<<NH, DP>>>();
    attn_out_kernel<<<dim3(CH, NH), 256>>>();
    gemm_out_kernel<<<dim3(8, 12), 256>>>(Wo, out);
}

// round 4
// speedup vs baseline: 1.9798x; 1.9198x over previous
#include <cuda_runtime.h>

typedef unsigned long long ull;

// Problem constants
#define LSEQ 512
#define NH 12
#define FD 16
#define HD 64
#define DM 768
#define DREAL 273
#define DP 288          // padded feature dim (zeros in 273..287)
#define CH 8            // number of chunks
#define CT 64           // chunk length
#define PROJ_N 1152     // q(192) | k(192) | v(768)
#define EPSV 1e-12f

// Scratch (device globals; no allocation allowed)
__device__ float g_P[LSEQ * PROJ_N];            // projection output
__device__ float g_phiQ[NH * LSEQ * DP];
__device__ float g_phiK[NH * LSEQ * DP];
__device__ float g_S[NH * CH * DP * HD];        // chunk KV sums -> exclusive prefix states
__device__ float g_Z[NH * CH * DP];             // chunk k sums  -> exclusive prefix
__device__ float g_Y[LSEQ * DM];                // attention output (pre-Wo)

// ---------------------------------------------------------------------------
// Packed f32x2 helpers
// ---------------------------------------------------------------------------
__device__ __forceinline__ ull dup2(float a) {
    ull r; asm("mov.b64 %0, {%1, %1};" : "=l"(r) : "f"(a)); return r;
}
__device__ __forceinline__ void fma2(ull& d, ull a, ull b) {
    asm("fma.rn.f32x2 %0, %1, %2, %0;" : "+l"(d) : "l"(a), "l"(b));
}
__device__ __forceinline__ float2 unpk(ull v) {
    float2 r; asm("mov.b64 {%0, %1}, %2;" : "=f"(r.x), "=f"(r.y) : "l"(v)); return r;
}

// ---------------------------------------------------------------------------
// Tiled fp32 GEMM: C[row0+m, coff+n] = sum_k A[row0+m,k] * B[n,k]
// BM=BN=64, BK=16, 256 threads, 4x4 micro-tile.
// A operand stored DUPLICATED in smem so FFMA2 needs no broadcast movs.
// ---------------------------------------------------------------------------
__device__ __forceinline__ void gemm_body(
    const float* __restrict__ A, const float* __restrict__ B,
    float* __restrict__ C, int K, int ldc, int coff, int row0)
{
    __shared__ __align__(16) float As2[2][16][132];   // [k][2*row] duplicated pairs
    __shared__ __align__(16) float Bs[2][16][68];
    const int tid = threadIdx.x;
    const int tx = tid & 15, ty = tid >> 4;
    const int ty8 = ty * 8, tx4 = tx * 4;
    const int lr = tid >> 2;            // 0..63
    const int lk = (tid & 3) * 4;       // 0,4,8,12

    ull acc[4][2];
#pragma unroll
    for (int i = 0; i < 4; i++) { acc[i][0] = 0ull; acc[i][1] = 0ull; }

    const float* ap = &A[(size_t)(row0 + lr) * K + lk];
    const float* bp = &B[(size_t)lr * K + lk];

    // preload tile 0
    {
        float4 av = *(const float4*)ap;
        float4 bv = *(const float4*)bp;
        *(float2*)&As2[0][lk + 0][2 * lr] = make_float2(av.x, av.x);
        *(float2*)&As2[0][lk + 1][2 * lr] = make_float2(av.y, av.y);
        *(float2*)&As2[0][lk + 2][2 * lr] = make_float2(av.z, av.z);
        *(float2*)&As2[0][lk + 3][2 * lr] = make_float2(av.w, av.w);
        Bs[0][lk + 0][lr] = bv.x; Bs[0][lk + 1][lr] = bv.y;
        Bs[0][lk + 2][lr] = bv.z; Bs[0][lk + 3][lr] = bv.w;
    }
    __syncthreads();

    int buf = 0;
    for (int k0 = 0; k0 < K; k0 += 16) {
        float4 av2, bv2;
        const bool more = (k0 + 16 < K);
        if (more) {
            av2 = *(const float4*)(ap + k0 + 16);
            bv2 = *(const float4*)(bp + k0 + 16);
        }
#pragma unroll
        for (int kk = 0; kk < 16; kk++) {
            ulonglong2 aP = *(const ulonglong2*)&As2[buf][kk][ty8];      // (a0,a0),(a1,a1)
            ulonglong2 aQ = *(const ulonglong2*)&As2[buf][kk][ty8 + 4];  // (a2,a2),(a3,a3)
            ulonglong2 b  = *(const ulonglong2*)&Bs[buf][kk][tx4];
            fma2(acc[0][0], aP.x, b.x); fma2(acc[0][1], aP.x, b.y);
            fma2(acc[1][0], aP.y, b.x); fma2(acc[1][1], aP.y, b.y);
            fma2(acc[2][0], aQ.x, b.x); fma2(acc[2][1], aQ.x, b.y);
            fma2(acc[3][0], aQ.y, b.x); fma2(acc[3][1], aQ.y, b.y);
        }
        if (more) {
            const int nb = buf ^ 1;
            *(float2*)&As2[nb][lk + 0][2 * lr] = make_float2(av2.x, av2.x);
            *(float2*)&As2[nb][lk + 1][2 * lr] = make_float2(av2.y, av2.y);
            *(float2*)&As2[nb][lk + 2][2 * lr] = make_float2(av2.z, av2.z);
            *(float2*)&As2[nb][lk + 3][2 * lr] = make_float2(av2.w, av2.w);
            Bs[nb][lk + 0][lr] = bv2.x; Bs[nb][lk + 1][lr] = bv2.y;
            Bs[nb][lk + 2][lr] = bv2.z; Bs[nb][lk + 3][lr] = bv2.w;
        }
        __syncthreads();
        buf ^= 1;
    }

#pragma unroll
    for (int i = 0; i < 4; i++) {
        float2 p0 = unpk(acc[i][0]);
        float2 p1 = unpk(acc[i][1]);
        float4 o; o.x = p0.x; o.y = p0.y; o.z = p1.x; o.w = p1.y;
        *(float4*)&C[(size_t)(row0 + ty * 4 + i) * ldc + coff + tx4] = o;
    }
}

// Fused q|k|v projection: grid (8, 18)
__global__ __launch_bounds__(256) void gemm_proj_fused(
    const float* __restrict__ hs, const float* __restrict__ Wq,
    const float* __restrict__ Wk, const float* __restrict__ Wv)
{
    const int cb = blockIdx.y;
    const float* B; int coff;
    if (cb < 3)      { B = Wq + (size_t)cb * 64 * DM;        coff = cb * 64; }
    else if (cb < 6) { B = Wk + (size_t)(cb - 3) * 64 * DM;  coff = 192 + (cb - 3) * 64; }
    else             { B = Wv + (size_t)(cb - 6) * 64 * DM;  coff = 384 + (cb - 6) * 64; }
    gemm_body(hs, B, g_P, DM, PROJ_N, coff, blockIdx.x * 64);
}

// Output projection: grid (8, 12)
__global__ __launch_bounds__(256) void gemm_out_kernel(
    const float* __restrict__ Wo, float* __restrict__ out)
{
    gemm_body(g_Y, Wo + (size_t)blockIdx.y * 64 * DM, out, DM, DM,
              blockIdx.y * 64, blockIdx.x * 64);
}

// ---------------------------------------------------------------------------
// Taylor feature map: phi = [1, x/2, x_i*x_j/(4*sqrt(2))], padded with zeros.
// ---------------------------------------------------------------------------
__global__ void phi_kernel()
{
    const int l = blockIdx.x, d = threadIdx.x;
    __shared__ float sx[384];
    for (int i = d; i < 384; i += 288) sx[i] = g_P[(size_t)l * PROJ_N + i];
    __syncthreads();

    int ii = 0, jj = 0, mode;
    if (d == 0) mode = 0;
    else if (d <= 16) { mode = 1; ii = d - 1; }
    else if (d < DREAL) { mode = 2; const int e = d - 17; ii = e >> 4; jj = e & 15; }
    else mode = 3;

    const float s = 0.17677669529663687f;   // 1/(4*sqrt(2))
    const size_t base = (size_t)l * DP + d;
#pragma unroll
    for (int h = 0; h < NH; h++) {
        const float* xq = &sx[h * FD];
        const float* xk = &sx[192 + h * FD];
        float vq, vk;
        if (mode == 0)      { vq = 1.f; vk = 1.f; }
        else if (mode == 1) { vq = xq[ii] * 0.5f; vk = xk[ii] * 0.5f; }
        else if (mode == 2) { vq = xq[ii] * xq[jj] * s; vk = xk[ii] * xk[jj] * s; }
        else                { vq = 0.f; vk = 0.f; }
        g_phiQ[(size_t)h * LSEQ * DP + base] = vq;
        g_phiK[(size_t)h * LSEQ * DP + base] = vk;
    }
}

// ---------------------------------------------------------------------------
// Per-chunk local sums: S_local[d][j] = sum_t phiK[t][d]*V[t][j]; z[d]=sum_t phiK
// grid (CH, NH), 288 threads (one per feature d), packed FFMA2
// ---------------------------------------------------------------------------
__global__ void chunk_kv_kernel()
{
    const int c = blockIdx.x, h = blockIdx.y;
    __shared__ __align__(16) float sV[CT][68];
    const int tid = threadIdx.x;
    for (int idx = tid; idx < CT * HD; idx += 288) {
        const int t = idx >> 6, j = idx & 63;
        sV[t][j] = g_P[(size_t)(c * CT + t) * PROJ_N + 384 + h * HD + j];
    }
    __syncthreads();

    const int d = tid;      // 0..287
    ull acc[32];
#pragma unroll
    for (int i = 0; i < 32; i++) acc[i] = 0ull;
    float zs = 0.f;

    const float* pk = &g_phiK[(size_t)(h * LSEQ + c * CT) * DP + d];
#pragma unroll 2
    for (int t = 0; t < CT; t++) {
        const float kd = pk[(size_t)t * DP];
        zs += kd;
        const ull kdp = dup2(kd);
#pragma unroll
        for (int j = 0; j < 16; j++) {
            ulonglong2 v = *(const ulonglong2*)&sV[t][j * 4];
            fma2(acc[2 * j + 0], kdp, v.x);
            fma2(acc[2 * j + 1], kdp, v.y);
        }
    }
    float* outp = &g_S[((size_t)(h * CH + c) * DP + d) * HD];
#pragma unroll
    for (int j = 0; j < 16; j++) {
        float2 p0 = unpk(acc[2 * j + 0]);
        float2 p1 = unpk(acc[2 * j + 1]);
        float4 o; o.x = p0.x; o.y = p0.y; o.z = p1.x; o.w = p1.y;
        *(float4*)&outp[j * 4] = o;
    }
    g_Z[(size_t)(h * CH + c) * DP + d] = zs;
}

// ---------------------------------------------------------------------------
// Parallel exclusive prefix over chunks.
// S: one thread per (h,d,j) lane — 221184 threads, MLP=8 front-batched loads.
// ---------------------------------------------------------------------------
__global__ __launch_bounds__(256) void prefix_S_kernel()
{
    const int idx = blockIdx.x * 256 + threadIdx.x;     // < NH*DP*HD
    const int h = idx / (DP * HD);
    const int r = idx - h * (DP * HD);
    const size_t base = (size_t)h * CH * DP * HD + r;
    float v[CH];
#pragma unroll
    for (int c = 0; c < CH; c++) v[c] = g_S[base + (size_t)c * DP * HD];
    float carry = 0.f;
#pragma unroll
    for (int c = 0; c < CH; c++) {
        g_S[base + (size_t)c * DP * HD] = carry;
        carry += v[c];
    }
}

__global__ __launch_bounds__(256) void prefix_Z_kernel()
{
    const int idx = blockIdx.x * 256 + threadIdx.x;
    if (idx >= NH * DP) return;
    const int h = idx / DP;
    const int d = idx - h * DP;
    const size_t base = (size_t)h * CH * DP + d;
    float v[CH];
#pragma unroll
    for (int c = 0; c < CH; c++) v[c] = g_Z[base + (size_t)c * DP];
    float carry = 0.f;
#pragma unroll
    for (int c = 0; c < CH; c++) {
        g_Z[base + (size_t)c * DP] = carry;
        carry += v[c];
    }
}

// ---------------------------------------------------------------------------
// Per-chunk attention output (dup-free FFMA2 via duplicated smem operands):
//   A = tril(phiQ phiK^T);  Y = phiQ @ S_prev + A @ V
//   den = phiQ . z_prev + rowsum(A) + eps;  y = Y / den
// grid (CH, NH), 256 threads
// ---------------------------------------------------------------------------
__global__ __launch_bounds__(256) void attn_out_kernel()
{
    const int c = blockIdx.x, h = blockIdx.y;
    __shared__ __align__(16) float sAd[CT][132];      // masked A, duplicated pairs
    __shared__ __align__(16) float sV[CT][68];
    __shared__ __align__(16) float sQt2[16][132];     // [feature][2*row] duplicated
    __shared__ __align__(16) float sKt[16][68];
    __shared__ __align__(16) float sS[16][68];
    __shared__ float sZ[16];
    __shared__ float sDen[CT];

    const int tid = threadIdx.x;
    const int tx = tid & 15, ty = tid >> 4;
    const int ty4 = ty * 4, tx4 = tx * 4, ty8 = ty * 8;
    const int lr = tid >> 2;
    const int lc = (tid & 3) * 4;

    // load V chunk
    for (int idx = tid; idx < CT * HD; idx += 256) {
        const int t = idx >> 6, j = idx & 63;
        sV[t][j] = g_P[(size_t)(c * CT + t) * PROJ_N + 384 + h * HD + j];
    }

    const float* phq = &g_phiQ[(size_t)(h * LSEQ + c * CT) * DP];
    const float* phk = &g_phiK[(size_t)(h * LSEQ + c * CT) * DP];
    const float* Sp = &g_S[(size_t)(h * CH + c) * DP * HD];
    const float* Zp = &g_Z[(size_t)(h * CH + c) * DP];

    ull accA[4][2], accY[4][2];
#pragma unroll
    for (int i = 0; i < 4; i++) {
        accA[i][0] = 0ull; accA[i][1] = 0ull;
        accY[i][0] = 0ull; accY[i][1] = 0ull;
    }
    float den0 = 0.f, den1 = 0.f, den2 = 0.f, den3 = 0.f;

    // prefetch first tile
    float4 qv = *(const float4*)&phq[(size_t)lr * DP + lc];
    float4 kv = *(const float4*)&phk[(size_t)lr * DP + lc];
    float4 sv = *(const float4*)&Sp[(size_t)ty * HD + tx4];
    float  zv = (tid < 16) ? Zp[tid] : 0.f;

    for (int d0 = 0; d0 < DP; d0 += 16) {
        // commit current tile to smem
        *(float2*)&sQt2[lc + 0][2 * lr] = make_float2(qv.x, qv.x);
        *(float2*)&sQt2[lc + 1][2 * lr] = make_float2(qv.y, qv.y);
        *(float2*)&sQt2[lc + 2][2 * lr] = make_float2(qv.z, qv.z);
        *(float2*)&sQt2[lc + 3][2 * lr] = make_float2(qv.w, qv.w);
        sKt[lc + 0][lr] = kv.x; sKt[lc + 1][lr] = kv.y;
        sKt[lc + 2][lr] = kv.z; sKt[lc + 3][lr] = kv.w;
        *(float4*)&sS[ty][tx4] = sv;
        if (tid < 16) sZ[tid] = zv;
        __syncthreads();

        // prefetch next tile (overlap with compute)
        const int dn = d0 + 16;
        if (dn < DP) {
            qv = *(const float4*)&phq[(size_t)lr * DP + dn + lc];
            kv = *(const float4*)&phk[(size_t)lr * DP + dn + lc];
            sv = *(const float4*)&Sp[(size_t)(dn + ty) * HD + tx4];
            if (tid < 16) zv = Zp[dn + tid];
        }

#pragma unroll
        for (int dd = 0; dd < 16; dd++) {
            ulonglong2 aP = *(const ulonglong2*)&sQt2[dd][ty8];      // (a0,a0),(a1,a1)
            ulonglong2 aQ = *(const ulonglong2*)&sQt2[dd][ty8 + 4];  // (a2,a2),(a3,a3)
            ulonglong2 kp = *(const ulonglong2*)&sKt[dd][tx4];
            ulonglong2 sp = *(const ulonglong2*)&sS[dd][tx4];
            fma2(accA[0][0], aP.x, kp.x); fma2(accA[0][1], aP.x, kp.y);
            fma2(accA[1][0], aP.y, kp.x); fma2(accA[1][1], aP.y, kp.y);
            fma2(accA[2][0], aQ.x, kp.x); fma2(accA[2][1], aQ.x, kp.y);
            fma2(accA[3][0], aQ.y, kp.x); fma2(accA[3][1], aQ.y, kp.y);
            fma2(accY[0][0], aP.x, sp.x); fma2(accY[0][1], aP.x, sp.y);
            fma2(accY[1][0], aP.y, sp.x); fma2(accY[1][1], aP.y, sp.y);
            fma2(accY[2][0], aQ.x, sp.x); fma2(accY[2][1], aQ.x, sp.y);
            fma2(accY[3][0], aQ.y, sp.x); fma2(accY[3][1], aQ.y, sp.y);
            if (tx == 0) {
                const float z = sZ[dd];
                den0 += unpk(aP.x).x * z; den1 += unpk(aP.y).x * z;
                den2 += unpk(aQ.x).x * z; den3 += unpk(aQ.y).x * z;
            }
        }
        __syncthreads();
    }

    // mask + store A (duplicated pairs for FFMA2 A.V loop)
#pragma unroll
    for (int i = 0; i < 4; i++) {
        float2 p0 = unpk(accA[i][0]);
        float2 p1 = unpk(accA[i][1]);
        const int t = ty4 + i;
        float m0 = (tx4 + 0 <= t) ? p0.x : 0.f;
        float m1 = (tx4 + 1 <= t) ? p0.y : 0.f;
        float m2 = (tx4 + 2 <= t) ? p1.x : 0.f;
        float m3 = (tx4 + 3 <= t) ? p1.y : 0.f;
        *(float2*)&sAd[t][2 * (tx4 + 0)] = make_float2(m0, m0);
        *(float2*)&sAd[t][2 * (tx4 + 1)] = make_float2(m1, m1);
        *(float2*)&sAd[t][2 * (tx4 + 2)] = make_float2(m2, m2);
        *(float2*)&sAd[t][2 * (tx4 + 3)] = make_float2(m3, m3);
    }
    __syncthreads();

    // Y += A @ V (A masked, duplicated)
#pragma unroll 4
    for (int s = 0; s < CT; s++) {
        ull a0 = *(const ull*)&sAd[ty4 + 0][2 * s];
        ull a1 = *(const ull*)&sAd[ty4 + 1][2 * s];
        ull a2 = *(const ull*)&sAd[ty4 + 2][2 * s];
        ull a3 = *(const ull*)&sAd[ty4 + 3][2 * s];
        ulonglong2 v = *(const ulonglong2*)&sV[s][tx4];
        fma2(accY[0][0], a0, v.x); fma2(accY[0][1], a0, v.y);
        fma2(accY[1][0], a1, v.x); fma2(accY[1][1], a1, v.y);
        fma2(accY[2][0], a2, v.x); fma2(accY[2][1], a2, v.y);
        fma2(accY[3][0], a3, v.x); fma2(accY[3][1], a3, v.y);
    }

    // den: add rowsums of masked A
    if (tx == 0) {
        float r0 = den0 + EPSV, r1 = den1 + EPSV, r2 = den2 + EPSV, r3 = den3 + EPSV;
#pragma unroll 8
        for (int s = 0; s < CT; s++) {
            r0 += sAd[ty4 + 0][2 * s];
            r1 += sAd[ty4 + 1][2 * s];
            r2 += sAd[ty4 + 2][2 * s];
            r3 += sAd[ty4 + 3][2 * s];
        }
        sDen[ty4 + 0] = r0; sDen[ty4 + 1] = r1; sDen[ty4 + 2] = r2; sDen[ty4 + 3] = r3;
    }
    __syncthreads();

    float* yo = &g_Y[(size_t)(c * CT) * DM + h * HD + tx4];
#pragma unroll
    for (int i = 0; i < 4; i++) {
        const float inv = 1.f / sDen[ty4 + i];
        float2 p0 = unpk(accY[i][0]);
        float2 p1 = unpk(accY[i][1]);
        float4 o;
        o.x = p0.x * inv; o.y = p0.y * inv; o.z = p1.x * inv; o.w = p1.y * inv;
        *(float4*)&yo[(size_t)(ty4 + i) * DM] = o;
    }
}

// ---------------------------------------------------------------------------
extern "C" void kernel_launch(void* const* d_in, const int* in_sizes, int n_in,
                              void* d_out, int out_size)
{
    const float* hs = (const float*)d_in[0];
    const float* Wq = (const float*)d_in[1];
    const float* Wk = (const float*)d_in[2];
    const float* Wv = (const float*)d_in[3];
    const float* Wo = (const float*)d_in[4];
    float* out = (float*)d_out;

    gemm_proj_fused<<<dim3(8, 18), 256>>>(hs, Wq, Wk, Wv);
    phi_kernel<<<LSEQ, DP>>>();
    chunk_kv_kernel<<<dim3(CH, NH), DP>>>();
    prefix_S_kernel<<<(NH * DP * HD) / 256, 256>>>();
    prefix_Z_kernel<<<(NH * DP + 255) / 256, 256>>>();
    attn_out_kernel<<<dim3(CH, NH), 256>>>();
    gemm_out_kernel<<<dim3(8, 12), 256>>>(Wo, out);
}